// round 14
// baseline (speedup 1.0000x reference)
#include <cuda_runtime.h>
#include <cuda_bf16.h>
#include <math.h>
#include <stdint.h>

#define NB 4
#define NT 2048
#define NC 1024
#define NH 64

// pre-split bf16 operands (hi + lo residual), 128B rows
__device__ __nv_bfloat16 g_wh[3*16*64*64];   // [w][chk][kr][n]
__device__ __nv_bfloat16 g_wl[3*16*64*64];
__device__ __nv_bfloat16 g_qh[NB*NT*NH], g_ql[NB*NT*NH];   // q pre-scaled
__device__ __nv_bfloat16 g_kh[NB*NT*NH], g_kl[NB*NT*NH];
__device__ __nv_bfloat16 g_vh[NB*NT*NH], g_vl[NB*NT*NH];
// split-K attention partials
__device__ float g_po[160*128*64];
__device__ float g_pl[160*128];

__constant__ uint8_t c_qt[40] = {15,15,15,15,14,14,14,14,13,13,13,13,12,12,12,12,
                                 11,11,11,10,10,10,9,9,9,8,8,8,7,7,6,6,5,5,4,4,3,2,1,0};
__constant__ uint8_t c_sp[40] = {0,1,2,3,0,1,2,3,0,1,2,3,0,1,2,3,
                                 0,1,2,0,1,2,0,1,2,0,1,2,0,1,0,1,0,1,0,1,0,0,0,0};
__constant__ uint8_t c_cnt[16] = {1,1,1,1,2,2,2,2,3,3,3,3,4,4,4,4};
__constant__ uint8_t c_cb[16]  = {39,38,37,36,34,32,30,28,25,22,19,16,12,8,4,0};

#define SWZ(o) ((o) ^ (((o) >> 3) & 0x70))

__device__ __forceinline__ uint32_t smem_u32(const void* p) {
    uint32_t a;
    asm("{ .reg .u64 t; cvta.to.shared.u64 t, %1; cvt.u32.u64 %0, t; }" : "=r"(a) : "l"(p));
    return a;
}
__device__ __forceinline__ uint32_t cvt2(float a, float b) {
    uint32_t r; asm("cvt.rn.bf16x2.f32 %0, %1, %2;" : "=r"(r) : "f"(b), "f"(a)); return r;
}
__device__ __forceinline__ void split4(float4 v, uint32_t& h01, uint32_t& h23,
                                       uint32_t& l01, uint32_t& l23) {
    h01 = cvt2(v.x, v.y); h23 = cvt2(v.z, v.w);
    float hx = __uint_as_float(h01 << 16), hy = __uint_as_float(h01 & 0xFFFF0000u);
    float hz = __uint_as_float(h23 << 16), hw = __uint_as_float(h23 & 0xFFFF0000u);
    l01 = cvt2(v.x - hx, v.y - hy); l23 = cvt2(v.z - hz, v.w - hw);
}
__device__ __forceinline__ void split2(float a, float b, uint32_t& h, uint32_t& l) {
    h = cvt2(a, b);
    l = cvt2(a - __uint_as_float(h << 16), b - __uint_as_float(h & 0xFFFF0000u));
}
__device__ __forceinline__ void sts64(uint32_t a, uint32_t x, uint32_t y) {
    asm volatile("st.shared.v2.b32 [%0], {%1,%2};" :: "r"(a), "r"(x), "r"(y));
}
__device__ __forceinline__ void cp16(uint32_t s, const void* g) {
    asm volatile("cp.async.cg.shared.global [%0], [%1], 16;" :: "r"(s), "l"(g) : "memory");
}
__device__ __forceinline__ void cp_commit() { asm volatile("cp.async.commit_group;" ::: "memory"); }
template<int N> __device__ __forceinline__ void cp_wait() { asm volatile("cp.async.wait_group %0;" :: "n"(N) : "memory"); }

__device__ __forceinline__ void ldm4(uint32_t* r, uint32_t a) {
    asm volatile("ldmatrix.sync.aligned.m8n8.x4.shared.b16 {%0,%1,%2,%3}, [%4];"
        : "=r"(r[0]), "=r"(r[1]), "=r"(r[2]), "=r"(r[3]) : "r"(a));
}
__device__ __forceinline__ void ldm4t(uint32_t* r, uint32_t a) {
    asm volatile("ldmatrix.sync.aligned.m8n8.x4.trans.shared.b16 {%0,%1,%2,%3}, [%4];"
        : "=r"(r[0]), "=r"(r[1]), "=r"(r[2]), "=r"(r[3]) : "r"(a));
}
__device__ __forceinline__ void mma_bf16(float* c, const uint32_t* a, const uint32_t* b) {
    asm volatile("mma.sync.aligned.m16n8k16.row.col.f32.bf16.bf16.f32 "
        "{%0,%1,%2,%3}, {%4,%5,%6,%7}, {%8,%9}, {%10,%11,%12,%13};"
        : "=f"(c[0]), "=f"(c[1]), "=f"(c[2]), "=f"(c[3])
        : "r"(a[0]), "r"(a[1]), "r"(a[2]), "r"(a[3]), "r"(b[0]), "r"(b[1]),
          "f"(c[0]), "f"(c[1]), "f"(c[2]), "f"(c[3]));
}
__device__ __forceinline__ uint32_t addrA(uint32_t base, int row0, int kbyte) {
    int ln = threadIdx.x & 31;
    int row = row0 + (ln & 15), kb = kbyte + (ln >> 4) * 16;
    return base + SWZ((uint32_t)(row * 128 + kb));
}
__device__ __forceinline__ uint32_t addrB(uint32_t base, int n0, int kbyte) {
    int ln = threadIdx.x & 31;
    int row = n0 + (ln & 7) + ((ln >> 4) << 3);
    int kb = kbyte + ((ln >> 3) & 1) * 16;
    return base + SWZ((uint32_t)(row * 128 + kb));
}
__device__ __forceinline__ uint32_t addrT(uint32_t base, int k0, int nbyte) {
    int ln = threadIdx.x & 31;
    int row = k0 + (ln & 7) + ((ln >> 3) & 1) * 8;
    int nb = nbyte + (ln >> 4) * 16;
    return base + SWZ((uint32_t)(row * 128 + nb));
}

// ============================================================================
// Kernel 0: split W into bf16 hi/lo (chunk-major). grid 48, block 256.
// ============================================================================
__global__ void __launch_bounds__(256) wsplit(const float* __restrict__ Wq,
        const float* __restrict__ Wk, const float* __restrict__ Wv) {
    const int w = blockIdx.x >> 4, chk = blockIdx.x & 15;
    const float* W = (w == 0) ? Wq : (w == 1 ? Wk : Wv);
    const float* src = W + (size_t)chk * 64 * 64;
    uint32_t* dh = (uint32_t*)(g_wh + (size_t)(w*16 + chk) * 4096);
    uint32_t* dl = (uint32_t*)(g_wl + (size_t)(w*16 + chk) * 4096);
    #pragma unroll
    for (int i = 0; i < 4; i++) {
        int idx = threadIdx.x + i * 256;          // float4 index, 1024 total
        float4 v = *(const float4*)(src + idx * 4);
        uint32_t h01, h23, l01, l23; split4(v, h01, h23, l01, l23);
        dh[idx*2] = h01; dh[idx*2+1] = h23;
        dl[idx*2] = l01; dl[idx*2+1] = l23;
    }
}

// ============================================================================
// Kernel 1: QKV. grid 128 (M=64), block 512. W via cp.async (pre-split),
// x via LDG+split. Outputs q(scaled)/k/v as bf16 hi/lo.
// ============================================================================
#define QK_XLO 8192
#define QK_W(w) (16384 + (w)*16384)   // hi; lo at +8192
#define QK_BUFSZ 65536
#define QK_SMEM (2*QK_BUFSZ)          // 128 KB

__global__ void __launch_bounds__(512, 1) qkv_tc(const float* __restrict__ x) {
    extern __shared__ char smem[];
    uint32_t sb = smem_u32(smem);
    const int tid = threadIdx.x, lane = tid & 31, warp = tid >> 5;
    const int wm = warp >> 2, wn = warp & 3;
    const int R0 = blockIdx.x * 64;

    float4 xr[2];
    float acc[6][4] = {};

    // cp.async W chunk: 3072 16B units (3 tensors x 2 halves x 512), 6/thread
    auto cpw = [&](int chk, uint32_t bufb) {
        #pragma unroll
        for (int i = 0; i < 6; i++) {
            int u = tid + i * 512;
            int w = u >> 10, h = (u >> 9) & 1, j = u & 511;
            int r = j >> 3, c = j & 7;
            const __nv_bfloat16* src = (h ? g_wl : g_wh)
                + (size_t)(w*16 + chk) * 4096 + r * 64 + c * 8;
            cp16(bufb + QK_W(w) + h * 8192 + SWZ((uint32_t)(r*128 + c*16)), src);
        }
        cp_commit();
    };
    auto ldgx = [&](int chk) {
        const float* xp = x + (size_t)R0 * NC + chk * 64;
        #pragma unroll
        for (int i = 0; i < 2; i++) {
            int idx = tid + i * 512, r = idx >> 4, c4 = idx & 15;
            xr[i] = *(const float4*)(xp + (size_t)r * NC + c4 * 4);
        }
    };
    auto stsx = [&](uint32_t bufb) {
        #pragma unroll
        for (int i = 0; i < 2; i++) {
            int idx = tid + i * 512, r = idx >> 4, c4 = idx & 15;
            uint32_t h01,h23,l01,l23; split4(xr[i], h01,h23,l01,l23);
            uint32_t off = SWZ((uint32_t)(r*128 + c4*8));
            sts64(bufb + off, h01, h23);
            sts64(bufb + QK_XLO + off, l01, l23);
        }
    };

    cpw(0, sb); ldgx(0); stsx(sb); cp_wait<0>(); __syncthreads();

    for (int chk = 0; chk < 16; chk++) {
        uint32_t bufb = sb + (uint32_t)(chk & 1) * QK_BUFSZ;
        uint32_t nbuf = sb + (uint32_t)((chk+1) & 1) * QK_BUFSZ;
        if (chk + 1 < 16) { cpw(chk + 1, nbuf); ldgx(chk + 1); }

        #pragma unroll
        for (int kk = 0; kk < 4; kk++) {
            uint32_t ah[4], al[4];
            ldm4(ah, addrA(bufb,           wm*16, kk*32));
            ldm4(al, addrA(bufb + QK_XLO,  wm*16, kk*32));
            #pragma unroll
            for (int jp = 0; jp < 3; jp++) {
                int gn = wn * 48 + jp * 16;
                uint32_t wb = bufb + QK_W(gn >> 6);
                int nb = (gn & 63) * 2;
                uint32_t bh[4], bl[4];
                ldm4t(bh, addrT(wb,        kk*16, nb));
                ldm4t(bl, addrT(wb + 8192, kk*16, nb));
                mma_bf16(acc[2*jp],   ah, bh);
                mma_bf16(acc[2*jp+1], ah, bh + 2);
                mma_bf16(acc[2*jp],   ah, bl);
                mma_bf16(acc[2*jp+1], ah, bl + 2);
                mma_bf16(acc[2*jp],   al, bh);
                mma_bf16(acc[2*jp+1], al, bh + 2);
            }
        }
        if (chk + 1 < 16) { stsx(nbuf); cp_wait<0>(); }
        __syncthreads();
    }

    // epilogue: split accumulators to bf16 hi/lo globals (q pre-scaled)
    __nv_bfloat16* outh[3] = {g_qh, g_kh, g_vh};
    __nv_bfloat16* outl[3] = {g_ql, g_kl, g_vl};
    int r0 = R0 + wm*16 + (lane >> 2);
    #pragma unroll
    for (int jp = 0; jp < 3; jp++)
        #pragma unroll
        for (int h = 0; h < 2; h++) {
            int gn = wn*48 + jp*16 + h*8 + 2*(lane & 3);
            int w = gn >> 6, n0 = gn & 63;
            float sc = (w == 0) ? 0.03125f : 1.0f;
            float* a = acc[jp*2+h];
            uint32_t hh, ll;
            split2(a[0]*sc, a[1]*sc, hh, ll);
            *(uint32_t*)(outh[w] + (size_t)r0*NH + n0) = hh;
            *(uint32_t*)(outl[w] + (size_t)r0*NH + n0) = ll;
            split2(a[2]*sc, a[3]*sc, hh, ll);
            *(uint32_t*)(outh[w] + (size_t)(r0+8)*NH + n0) = hh;
            *(uint32_t*)(outl[w] + (size_t)(r0+8)*NH + n0) = ll;
        }
}

// ============================================================================
// Kernel 2: causal attention, split-K. grid (40,4), block 256.
// All operands pre-split bf16 -> pure cp.async + ldmatrix + MMA + exp.
// ============================================================================
#define AT_QLO 16384
#define AT_KV(bu) (32768u + (bu)*32768u)   // KH+0 KL+8192 VH+16384 VL+24576
#define AT_SMEM (32768 + 2*32768)

__global__ void __launch_bounds__(256, 1) attn_tc() {
    extern __shared__ char smem[];
    uint32_t sb = smem_u32(smem);
    const int tid = threadIdx.x, lane = tid & 31, warp = tid >> 5;
    const int c = blockIdx.x, b = blockIdx.y;
    const int qt = c_qt[c], sp = c_sp[c];
    const int cnt = c_cnt[qt];
    const int nk = 2*qt + 2;
    const int per = (nk + cnt - 1) / cnt;
    const int k0 = sp * per;
    const int k1 = (k0 + per < nk) ? (k0 + per) : nk;

    const size_t boff = (size_t)b * NT * NH;
    const __nv_bfloat16* kh = g_kh + boff; const __nv_bfloat16* kl = g_kl + boff;
    const __nv_bfloat16* vh = g_vh + boff; const __nv_bfloat16* vl = g_vl + boff;

    // cp.async one KV tile (32KB): 2048 units, 8/thread
    auto cpkv = [&](int kt, uint32_t dst) {
        const __nv_bfloat16* srcs[4] = {kh + (size_t)kt*64*NH, kl + (size_t)kt*64*NH,
                                        vh + (size_t)kt*64*NH, vl + (size_t)kt*64*NH};
        #pragma unroll
        for (int i = 0; i < 8; i++) {
            int u = tid + i * 256;
            int t = u >> 9, j = u & 511;     // t: 0=KH 1=KL 2=VH 3=VL
            int r = j >> 3, cc = j & 7;
            cp16(dst + t * 8192 + SWZ((uint32_t)(r*128 + cc*16)), srcs[t] + r*64 + cc*8);
        }
    };

    // prologue: Q (both halves) + KV(k0) in one cp group
    {
        const __nv_bfloat16* qsrc[2] = {g_qh + boff + (size_t)qt*128*NH,
                                        g_ql + boff + (size_t)qt*128*NH};
        #pragma unroll
        for (int i = 0; i < 8; i++) {
            int u = tid + i * 256;
            int h = u >> 10, j = u & 1023;
            int r = j >> 3, cc = j & 7;
            cp16(sb + h * 16384 + SWZ((uint32_t)(r*128 + cc*16)), qsrc[h] + r*64 + cc*8);
        }
        cpkv(k0, sb + AT_KV(0));
        cp_commit();
        cp_wait<0>();
    }
    __syncthreads();

    uint32_t qh[4][4], ql[4][4];
    #pragma unroll
    for (int kk = 0; kk < 4; kk++) {
        ldm4(qh[kk], addrA(sb,          warp*16, kk*32));
        ldm4(ql[kk], addrA(sb + AT_QLO, warp*16, kk*32));
    }

    float o[8][4] = {};
    float l0 = 0.f, l1 = 0.f;
    const int lr   = warp*16 + (lane >> 2);
    const int rowA = qt*128 + lr;
    const int rowB = rowA + 8;

    for (int kt = k0; kt < k1; kt++) {
        const int it = kt - k0;
        uint32_t kvb = sb + AT_KV(it & 1);
        bool pf = (kt + 1 < k1);
        if (pf) { cpkv(kt + 1, sb + AT_KV((it + 1) & 1)); cp_commit(); }

        // S = Q K^T
        float s[8][4] = {};
        #pragma unroll
        for (int kk = 0; kk < 4; kk++) {
            uint32_t bh[16], bl[16];
            #pragma unroll
            for (int jp = 0; jp < 4; jp++) {
                ldm4(bh + jp*4, addrB(kvb,        jp*16, kk*32));
                ldm4(bl + jp*4, addrB(kvb + 8192, jp*16, kk*32));
            }
            #pragma unroll
            for (int j = 0; j < 8; j++) {
                mma_bf16(s[j], qh[kk], bh + j*2);
                mma_bf16(s[j], qh[kk], bl + j*2);
                mma_bf16(s[j], ql[kk], bh + j*2);
            }
        }

        // exp + row-sum + pack P fragments (registers only)
        uint32_t pah[4][4], pal[4][4];
        bool domask = (kt*64 + 63 > qt*128 + warp*16);
        #pragma unroll
        for (int j = 0; j < 8; j++) {
            int col = kt*64 + j*8 + 2*(lane & 3);
            float p0, p1, p2, p3;
            if (domask) {
                p0 = (col     <= rowA) ? __expf(s[j][0]) : 0.f;
                p1 = (col + 1 <= rowA) ? __expf(s[j][1]) : 0.f;
                p2 = (col     <= rowB) ? __expf(s[j][2]) : 0.f;
                p3 = (col + 1 <= rowB) ? __expf(s[j][3]) : 0.f;
            } else {
                p0 = __expf(s[j][0]); p1 = __expf(s[j][1]);
                p2 = __expf(s[j][2]); p3 = __expf(s[j][3]);
            }
            l0 += p0 + p1; l1 += p2 + p3;
            uint32_t h01, q01, h23, q23;
            split2(p0, p1, h01, q01);
            split2(p2, p3, h23, q23);
            pah[j >> 1][(j & 1)*2]     = h01;
            pah[j >> 1][(j & 1)*2 + 1] = h23;
            pal[j >> 1][(j & 1)*2]     = q01;
            pal[j >> 1][(j & 1)*2 + 1] = q23;
        }

        // O += P V
        #pragma unroll
        for (int kk = 0; kk < 4; kk++) {
            uint32_t vhf[16], vlf[16];
            #pragma unroll
            for (int jp = 0; jp < 4; jp++) {
                ldm4t(vhf + jp*4, addrT(kvb + 16384, kk*16, jp*32));
                ldm4t(vlf + jp*4, addrT(kvb + 24576, kk*16, jp*32));
            }
            #pragma unroll
            for (int j = 0; j < 8; j++) {
                mma_bf16(o[j], pah[kk], vhf + j*2);
                mma_bf16(o[j], pah[kk], vlf + j*2);
                mma_bf16(o[j], pal[kk], vhf + j*2);
            }
        }

        if (pf) cp_wait<0>();
        __syncthreads();
    }

    // epilogue: quad-reduce row sums; write partial O + l to scratch
    l0 += __shfl_xor_sync(0xffffffffu, l0, 1);
    l0 += __shfl_xor_sync(0xffffffffu, l0, 2);
    l1 += __shfl_xor_sync(0xffffffffu, l1, 1);
    l1 += __shfl_xor_sync(0xffffffffu, l1, 2);

    const uint32_t u = (uint32_t)b * 40 + c;
    if ((lane & 3) == 0) {
        g_pl[u*128 + lr]     = l0;
        g_pl[u*128 + lr + 8] = l1;
    }
    float* pb = g_po + (size_t)u * 8192 + (size_t)lr * 64;
    #pragma unroll
    for (int j = 0; j < 8; j++) {
        int col = j*8 + 2*(lane & 3);
        *(float2*)(pb + col)        = make_float2(o[j][0], o[j][1]);
        *(float2*)(pb + 8*64 + col) = make_float2(o[j][2], o[j][3]);
    }
}

// ============================================================================
// Kernel 3: combine partials. grid (16,4), block 256.
// ============================================================================
__global__ void __launch_bounds__(256) combine(float* __restrict__ out) {
    const int qt = blockIdx.x, b = blockIdx.y;
    const int cnt = c_cnt[qt], cb = c_cb[qt];
    const int tid = threadIdx.x;
    __shared__ float ls[128];

    if (tid < 128) {
        float s = 0.f;
        for (int i = 0; i < cnt; i++)
            s += g_pl[((uint32_t)b*40 + cb + i)*128 + tid];
        ls[tid] = s;
    }
    __syncthreads();

    const int row = tid >> 1, col0 = (tid & 1) * 32;
    float4 acc[8] = {};
    for (int i = 0; i < cnt; i++) {
        const float* pb = g_po + (size_t)((uint32_t)b*40 + cb + i) * 8192
                        + (size_t)row * 64 + col0;
        #pragma unroll
        for (int j = 0; j < 8; j++) {
            float4 v = *(const float4*)(pb + j*4);
            acc[j].x += v.x; acc[j].y += v.y; acc[j].z += v.z; acc[j].w += v.w;
        }
    }
    float inv = 1.0f / ls[row];
    float* ob = out + ((size_t)b * NT + (size_t)qt * 128 + row) * NH + col0;
    #pragma unroll
    for (int j = 0; j < 8; j++)
        *(float4*)(ob + j*4) = make_float4(acc[j].x*inv, acc[j].y*inv,
                                           acc[j].z*inv, acc[j].w*inv);
}

// ---------------------------------------------------------------------------
extern "C" void kernel_launch(void* const* d_in, const int* in_sizes, int n_in,
                              void* d_out, int out_size) {
    const float* x  = (const float*)d_in[0];
    const float* Wq = (const float*)d_in[1];
    const float* Wk = (const float*)d_in[2];
    const float* Wv = (const float*)d_in[3];
    float* out = (float*)d_out;

    wsplit<<<48, 256>>>(Wq, Wk, Wv);

    cudaFuncSetAttribute(qkv_tc, cudaFuncAttributeMaxDynamicSharedMemorySize, QK_SMEM);
    qkv_tc<<<128, 512, QK_SMEM>>>(x);

    cudaFuncSetAttribute(attn_tc, cudaFuncAttributeMaxDynamicSharedMemorySize, AT_SMEM);
    attn_tc<<<dim3(40, NB), 256, AT_SMEM>>>();

    combine<<<dim3(16, NB), 256>>>(out);
}

// round 15
// speedup vs baseline: 1.0466x; 1.0466x over previous
#include <cuda_runtime.h>
#include <cuda_bf16.h>
#include <math.h>
#include <stdint.h>

#define NB 4
#define NT 2048
#define NC 1024
#define NH 64

// pre-split bf16 operands (hi + lo residual)
__device__ __nv_bfloat16 g_wh[3*16*64*64];   // [w][chk][kr][n]
__device__ __nv_bfloat16 g_wl[3*16*64*64];
__device__ __nv_bfloat16 g_qh[NB*NT*NH], g_ql[NB*NT*NH];   // q pre-scaled
__device__ __nv_bfloat16 g_kh[NB*NT*NH], g_kl[NB*NT*NH];
__device__ __nv_bfloat16 g_vh[NB*NT*NH], g_vl[NB*NT*NH];
// split-K attention partials
__device__ float g_po[160*128*64];
__device__ float g_pl[160*128];

__constant__ uint8_t c_qt[40] = {15,15,15,15,14,14,14,14,13,13,13,13,12,12,12,12,
                                 11,11,11,10,10,10,9,9,9,8,8,8,7,7,6,6,5,5,4,4,3,2,1,0};
__constant__ uint8_t c_sp[40] = {0,1,2,3,0,1,2,3,0,1,2,3,0,1,2,3,
                                 0,1,2,0,1,2,0,1,2,0,1,2,0,1,0,1,0,1,0,1,0,0,0,0};
__constant__ uint8_t c_cnt[16] = {1,1,1,1,2,2,2,2,3,3,3,3,4,4,4,4};
__constant__ uint8_t c_cb[16]  = {39,38,37,36,34,32,30,28,25,22,19,16,12,8,4,0};

#define SWZ(o) ((o) ^ (((o) >> 3) & 0x70))

__device__ __forceinline__ uint32_t smem_u32(const void* p) {
    uint32_t a;
    asm("{ .reg .u64 t; cvta.to.shared.u64 t, %1; cvt.u32.u64 %0, t; }" : "=r"(a) : "l"(p));
    return a;
}
__device__ __forceinline__ uint32_t cvt2(float a, float b) {
    uint32_t r; asm("cvt.rn.bf16x2.f32 %0, %1, %2;" : "=r"(r) : "f"(b), "f"(a)); return r;
}
__device__ __forceinline__ void split4(float4 v, uint32_t& h01, uint32_t& h23,
                                       uint32_t& l01, uint32_t& l23) {
    h01 = cvt2(v.x, v.y); h23 = cvt2(v.z, v.w);
    float hx = __uint_as_float(h01 << 16), hy = __uint_as_float(h01 & 0xFFFF0000u);
    float hz = __uint_as_float(h23 << 16), hw = __uint_as_float(h23 & 0xFFFF0000u);
    l01 = cvt2(v.x - hx, v.y - hy); l23 = cvt2(v.z - hz, v.w - hw);
}
__device__ __forceinline__ void split2(float a, float b, uint32_t& h, uint32_t& l) {
    h = cvt2(a, b);
    l = cvt2(a - __uint_as_float(h << 16), b - __uint_as_float(h & 0xFFFF0000u));
}
__device__ __forceinline__ void sts64(uint32_t a, uint32_t x, uint32_t y) {
    asm volatile("st.shared.v2.b32 [%0], {%1,%2};" :: "r"(a), "r"(x), "r"(y));
}
__device__ __forceinline__ void cp16(uint32_t s, const void* g) {
    asm volatile("cp.async.cg.shared.global [%0], [%1], 16;" :: "r"(s), "l"(g) : "memory");
}
__device__ __forceinline__ void cp_commit() { asm volatile("cp.async.commit_group;" ::: "memory"); }
template<int N> __device__ __forceinline__ void cp_wait() { asm volatile("cp.async.wait_group %0;" :: "n"(N) : "memory"); }

__device__ __forceinline__ void ldm4(uint32_t* r, uint32_t a) {
    asm volatile("ldmatrix.sync.aligned.m8n8.x4.shared.b16 {%0,%1,%2,%3}, [%4];"
        : "=r"(r[0]), "=r"(r[1]), "=r"(r[2]), "=r"(r[3]) : "r"(a));
}
__device__ __forceinline__ void ldm4t(uint32_t* r, uint32_t a) {
    asm volatile("ldmatrix.sync.aligned.m8n8.x4.trans.shared.b16 {%0,%1,%2,%3}, [%4];"
        : "=r"(r[0]), "=r"(r[1]), "=r"(r[2]), "=r"(r[3]) : "r"(a));
}
__device__ __forceinline__ void mma_bf16(float* c, const uint32_t* a, const uint32_t* b) {
    asm volatile("mma.sync.aligned.m16n8k16.row.col.f32.bf16.bf16.f32 "
        "{%0,%1,%2,%3}, {%4,%5,%6,%7}, {%8,%9}, {%10,%11,%12,%13};"
        : "=f"(c[0]), "=f"(c[1]), "=f"(c[2]), "=f"(c[3])
        : "r"(a[0]), "r"(a[1]), "r"(a[2]), "r"(a[3]), "r"(b[0]), "r"(b[1]),
          "f"(c[0]), "f"(c[1]), "f"(c[2]), "f"(c[3]));
}
__device__ __forceinline__ uint32_t addrA(uint32_t base, int row0, int kbyte) {
    int ln = threadIdx.x & 31;
    int row = row0 + (ln & 15), kb = kbyte + (ln >> 4) * 16;
    return base + SWZ((uint32_t)(row * 128 + kb));
}
__device__ __forceinline__ uint32_t addrB(uint32_t base, int n0, int kbyte) {
    int ln = threadIdx.x & 31;
    int row = n0 + (ln & 7) + ((ln >> 4) << 3);
    int kb = kbyte + ((ln >> 3) & 1) * 16;
    return base + SWZ((uint32_t)(row * 128 + kb));
}
__device__ __forceinline__ uint32_t addrT(uint32_t base, int k0, int nbyte) {
    int ln = threadIdx.x & 31;
    int row = k0 + (ln & 7) + ((ln >> 3) & 1) * 8;
    int nb = nbyte + (ln >> 4) * 16;
    return base + SWZ((uint32_t)(row * 128 + nb));
}

// ============================================================================
// Kernel 0: split W into bf16 hi/lo (chunk-major). grid 48, block 256.
// ============================================================================
__global__ void __launch_bounds__(256) wsplit(const float* __restrict__ Wq,
        const float* __restrict__ Wk, const float* __restrict__ Wv) {
    const int w = blockIdx.x >> 4, chk = blockIdx.x & 15;
    const float* W = (w == 0) ? Wq : (w == 1 ? Wk : Wv);
    const float* src = W + (size_t)chk * 64 * 64;
    uint32_t* dh = (uint32_t*)(g_wh + (size_t)(w*16 + chk) * 4096);
    uint32_t* dl = (uint32_t*)(g_wl + (size_t)(w*16 + chk) * 4096);
    #pragma unroll
    for (int i = 0; i < 4; i++) {
        int idx = threadIdx.x + i * 256;
        float4 v = *(const float4*)(src + idx * 4);
        uint32_t h01, h23, l01, l23; split4(v, h01, h23, l01, l23);
        dh[idx*2] = h01; dh[idx*2+1] = h23;
        dl[idx*2] = l01; dl[idx*2+1] = l23;
    }
}

// ============================================================================
// Kernel 1: QKV. grid 128 (M=64), block 512. W via cp.async (pre-split),
// x via LDG+split. Outputs q(scaled)/k/v as bf16 hi/lo.
// ============================================================================
#define QK_XLO 8192
#define QK_W(w) (16384 + (w)*16384)   // hi; lo at +8192
#define QK_BUFSZ 65536
#define QK_SMEM (2*QK_BUFSZ)          // 128 KB

__global__ void __launch_bounds__(512, 1) qkv_tc(const float* __restrict__ x) {
    extern __shared__ char smem[];
    uint32_t sb = smem_u32(smem);
    const int tid = threadIdx.x, lane = tid & 31, warp = tid >> 5;
    const int wm = warp >> 2, wn = warp & 3;
    const int R0 = blockIdx.x * 64;

    float4 xr[2];
    float acc[6][4] = {};

    auto cpw = [&](int chk, uint32_t bufb) {
        #pragma unroll
        for (int i = 0; i < 6; i++) {
            int u = tid + i * 512;
            int w = u >> 10, h = (u >> 9) & 1, j = u & 511;
            int r = j >> 3, c = j & 7;
            const __nv_bfloat16* src = (h ? g_wl : g_wh)
                + (size_t)(w*16 + chk) * 4096 + r * 64 + c * 8;
            cp16(bufb + QK_W(w) + h * 8192 + SWZ((uint32_t)(r*128 + c*16)), src);
        }
        cp_commit();
    };
    auto ldgx = [&](int chk) {
        const float* xp = x + (size_t)R0 * NC + chk * 64;
        #pragma unroll
        for (int i = 0; i < 2; i++) {
            int idx = tid + i * 512, r = idx >> 4, c4 = idx & 15;
            xr[i] = *(const float4*)(xp + (size_t)r * NC + c4 * 4);
        }
    };
    auto stsx = [&](uint32_t bufb) {
        #pragma unroll
        for (int i = 0; i < 2; i++) {
            int idx = tid + i * 512, r = idx >> 4, c4 = idx & 15;
            uint32_t h01,h23,l01,l23; split4(xr[i], h01,h23,l01,l23);
            uint32_t off = SWZ((uint32_t)(r*128 + c4*8));
            sts64(bufb + off, h01, h23);
            sts64(bufb + QK_XLO + off, l01, l23);
        }
    };

    cpw(0, sb); ldgx(0); stsx(sb); cp_wait<0>(); __syncthreads();

    for (int chk = 0; chk < 16; chk++) {
        uint32_t bufb = sb + (uint32_t)(chk & 1) * QK_BUFSZ;
        uint32_t nbuf = sb + (uint32_t)((chk+1) & 1) * QK_BUFSZ;
        if (chk + 1 < 16) { cpw(chk + 1, nbuf); ldgx(chk + 1); }

        #pragma unroll
        for (int kk = 0; kk < 4; kk++) {
            uint32_t ah[4], al[4];
            ldm4(ah, addrA(bufb,           wm*16, kk*32));
            ldm4(al, addrA(bufb + QK_XLO,  wm*16, kk*32));
            #pragma unroll
            for (int jp = 0; jp < 3; jp++) {
                int gn = wn * 48 + jp * 16;
                uint32_t wb = bufb + QK_W(gn >> 6);
                int nb = (gn & 63) * 2;
                uint32_t bh[4], bl[4];
                ldm4t(bh, addrT(wb,        kk*16, nb));
                ldm4t(bl, addrT(wb + 8192, kk*16, nb));
                mma_bf16(acc[2*jp],   ah, bh);
                mma_bf16(acc[2*jp+1], ah, bh + 2);
                mma_bf16(acc[2*jp],   ah, bl);
                mma_bf16(acc[2*jp+1], ah, bl + 2);
                mma_bf16(acc[2*jp],   al, bh);
                mma_bf16(acc[2*jp+1], al, bh + 2);
            }
        }
        if (chk + 1 < 16) { stsx(nbuf); cp_wait<0>(); }
        __syncthreads();
    }

    __nv_bfloat16* outh[3] = {g_qh, g_kh, g_vh};
    __nv_bfloat16* outl[3] = {g_ql, g_kl, g_vl};
    int r0 = R0 + wm*16 + (lane >> 2);
    #pragma unroll
    for (int jp = 0; jp < 3; jp++)
        #pragma unroll
        for (int h = 0; h < 2; h++) {
            int gn = wn*48 + jp*16 + h*8 + 2*(lane & 3);
            int w = gn >> 6, n0 = gn & 63;
            float sc = (w == 0) ? 0.03125f : 1.0f;
            float* a = acc[jp*2+h];
            uint32_t hh, ll;
            split2(a[0]*sc, a[1]*sc, hh, ll);
            *(uint32_t*)(outh[w] + (size_t)r0*NH + n0) = hh;
            *(uint32_t*)(outl[w] + (size_t)r0*NH + n0) = ll;
            split2(a[2]*sc, a[3]*sc, hh, ll);
            *(uint32_t*)(outh[w] + (size_t)(r0+8)*NH + n0) = hh;
            *(uint32_t*)(outl[w] + (size_t)(r0+8)*NH + n0) = ll;
        }
}

// ============================================================================
// Kernel 2: causal attention, split-K. grid (40,4), block 256.
// cnt==1 units (qt 0..3) normalize and write out directly; others -> scratch.
// ============================================================================
#define AT_QLO 16384
#define AT_KV(bu) (32768u + (bu)*32768u)   // KH+0 KL+8192 VH+16384 VL+24576
#define AT_SMEM (32768 + 2*32768)

__global__ void __launch_bounds__(256, 1) attn_tc(float* __restrict__ out) {
    extern __shared__ char smem[];
    uint32_t sb = smem_u32(smem);
    const int tid = threadIdx.x, lane = tid & 31, warp = tid >> 5;
    const int c = blockIdx.x, b = blockIdx.y;
    const int qt = c_qt[c], sp = c_sp[c];
    const int cnt = c_cnt[qt];
    const int nk = 2*qt + 2;
    const int per = (nk + cnt - 1) / cnt;
    const int k0 = sp * per;
    const int k1 = (k0 + per < nk) ? (k0 + per) : nk;

    const size_t boff = (size_t)b * NT * NH;
    const __nv_bfloat16* kh = g_kh + boff; const __nv_bfloat16* kl = g_kl + boff;
    const __nv_bfloat16* vh = g_vh + boff; const __nv_bfloat16* vl = g_vl + boff;

    auto cpkv = [&](int kt, uint32_t dst) {
        const __nv_bfloat16* srcs[4] = {kh + (size_t)kt*64*NH, kl + (size_t)kt*64*NH,
                                        vh + (size_t)kt*64*NH, vl + (size_t)kt*64*NH};
        #pragma unroll
        for (int i = 0; i < 8; i++) {
            int u = tid + i * 256;
            int t = u >> 9, j = u & 511;
            int r = j >> 3, cc = j & 7;
            cp16(dst + t * 8192 + SWZ((uint32_t)(r*128 + cc*16)), srcs[t] + r*64 + cc*8);
        }
    };

    {
        const __nv_bfloat16* qsrc[2] = {g_qh + boff + (size_t)qt*128*NH,
                                        g_ql + boff + (size_t)qt*128*NH};
        #pragma unroll
        for (int i = 0; i < 8; i++) {
            int u = tid + i * 256;
            int h = u >> 10, j = u & 1023;
            int r = j >> 3, cc = j & 7;
            cp16(sb + h * 16384 + SWZ((uint32_t)(r*128 + cc*16)), qsrc[h] + r*64 + cc*8);
        }
        cpkv(k0, sb + AT_KV(0));
        cp_commit();
        cp_wait<0>();
    }
    __syncthreads();

    uint32_t qh[4][4], ql[4][4];
    #pragma unroll
    for (int kk = 0; kk < 4; kk++) {
        ldm4(qh[kk], addrA(sb,          warp*16, kk*32));
        ldm4(ql[kk], addrA(sb + AT_QLO, warp*16, kk*32));
    }

    float o[8][4] = {};
    float l0 = 0.f, l1 = 0.f;
    const int lr   = warp*16 + (lane >> 2);
    const int rowA = qt*128 + lr;
    const int rowB = rowA + 8;

    for (int kt = k0; kt < k1; kt++) {
        const int it = kt - k0;
        uint32_t kvb = sb + AT_KV(it & 1);
        bool pf = (kt + 1 < k1);
        if (pf) { cpkv(kt + 1, sb + AT_KV((it + 1) & 1)); cp_commit(); }

        // S = Q K^T
        float s[8][4] = {};
        #pragma unroll
        for (int kk = 0; kk < 4; kk++) {
            uint32_t bh[16], bl[16];
            #pragma unroll
            for (int jp = 0; jp < 4; jp++) {
                ldm4(bh + jp*4, addrB(kvb,        jp*16, kk*32));
                ldm4(bl + jp*4, addrB(kvb + 8192, jp*16, kk*32));
            }
            #pragma unroll
            for (int j = 0; j < 8; j++) {
                mma_bf16(s[j], qh[kk], bh + j*2);
                mma_bf16(s[j], qh[kk], bl + j*2);
                mma_bf16(s[j], ql[kk], bh + j*2);
            }
        }

        // exp + row-sum + pack P fragments (registers only)
        uint32_t pah[4][4], pal[4][4];
        bool domask = (kt*64 + 63 > qt*128 + warp*16);
        #pragma unroll
        for (int j = 0; j < 8; j++) {
            int col = kt*64 + j*8 + 2*(lane & 3);
            float p0, p1, p2, p3;
            if (domask) {
                p0 = (col     <= rowA) ? __expf(s[j][0]) : 0.f;
                p1 = (col + 1 <= rowA) ? __expf(s[j][1]) : 0.f;
                p2 = (col     <= rowB) ? __expf(s[j][2]) : 0.f;
                p3 = (col + 1 <= rowB) ? __expf(s[j][3]) : 0.f;
            } else {
                p0 = __expf(s[j][0]); p1 = __expf(s[j][1]);
                p2 = __expf(s[j][2]); p3 = __expf(s[j][3]);
            }
            l0 += p0 + p1; l1 += p2 + p3;
            uint32_t h01, q01, h23, q23;
            split2(p0, p1, h01, q01);
            split2(p2, p3, h23, q23);
            pah[j >> 1][(j & 1)*2]     = h01;
            pah[j >> 1][(j & 1)*2 + 1] = h23;
            pal[j >> 1][(j & 1)*2]     = q01;
            pal[j >> 1][(j & 1)*2 + 1] = q23;
        }

        // O += P V
        #pragma unroll
        for (int kk = 0; kk < 4; kk++) {
            uint32_t vhf[16], vlf[16];
            #pragma unroll
            for (int jp = 0; jp < 4; jp++) {
                ldm4t(vhf + jp*4, addrT(kvb + 16384, kk*16, jp*32));
                ldm4t(vlf + jp*4, addrT(kvb + 24576, kk*16, jp*32));
            }
            #pragma unroll
            for (int j = 0; j < 8; j++) {
                mma_bf16(o[j], pah[kk], vhf + j*2);
                mma_bf16(o[j], pah[kk], vlf + j*2);
                mma_bf16(o[j], pal[kk], vhf + j*2);
            }
        }

        if (pf) cp_wait<0>();
        __syncthreads();
    }

    // epilogue: quad-reduce row sums
    l0 += __shfl_xor_sync(0xffffffffu, l0, 1);
    l0 += __shfl_xor_sync(0xffffffffu, l0, 2);
    l1 += __shfl_xor_sync(0xffffffffu, l1, 1);
    l1 += __shfl_xor_sync(0xffffffffu, l1, 2);

    if (cnt == 1) {
        // complete k-range: normalize and write final output directly
        float i0 = 1.0f / l0, i1 = 1.0f / l1;
        float* ob = out + ((size_t)b * NT + rowA) * NH;
        #pragma unroll
        for (int j = 0; j < 8; j++) {
            int col = j*8 + 2*(lane & 3);
            *(float2*)(ob + col)        = make_float2(o[j][0]*i0, o[j][1]*i0);
            *(float2*)(ob + 8*NH + col) = make_float2(o[j][2]*i1, o[j][3]*i1);
        }
    } else {
        const uint32_t u = (uint32_t)b * 40 + c;
        if ((lane & 3) == 0) {
            g_pl[u*128 + lr]     = l0;
            g_pl[u*128 + lr + 8] = l1;
        }
        float* pb = g_po + (size_t)u * 8192 + (size_t)lr * 64;
        #pragma unroll
        for (int j = 0; j < 8; j++) {
            int col = j*8 + 2*(lane & 3);
            *(float2*)(pb + col)        = make_float2(o[j][0], o[j][1]);
            *(float2*)(pb + 8*64 + col) = make_float2(o[j][2], o[j][3]);
        }
    }
}

// ============================================================================
// Kernel 3: combine partials for qt 4..15 only. grid (24, NB), block 256.
// blockIdx.x: qtIdx*2 + rowhalf. Each block: 64 rows x 64 cols.
// ============================================================================
__global__ void __launch_bounds__(256) combine(float* __restrict__ out) {
    const int qt = 4 + (blockIdx.x >> 1);
    const int half = blockIdx.x & 1;
    const int b = blockIdx.y;
    const int cnt = c_cnt[qt], cb = c_cb[qt];
    const int tid = threadIdx.x;
    __shared__ float ls[64];

    if (tid < 64) {
        float s = 0.f;
        #pragma unroll 4
        for (int i = 0; i < cnt; i++)
            s += g_pl[((uint32_t)b*40 + cb + i)*128 + half*64 + tid];
        ls[tid] = s;
    }
    __syncthreads();

    const int rl = tid >> 2;                 // 0..63
    const int grow = half*64 + rl;           // row within q-tile
    const int col0 = (tid & 3) * 16;
    float4 acc[4] = {};
    #pragma unroll 4
    for (int i = 0; i < cnt; i++) {
        const float* pb = g_po + (size_t)((uint32_t)b*40 + cb + i) * 8192
                        + (size_t)grow * 64 + col0;
        #pragma unroll
        for (int j = 0; j < 4; j++) {
            float4 v = *(const float4*)(pb + j*4);
            acc[j].x += v.x; acc[j].y += v.y; acc[j].z += v.z; acc[j].w += v.w;
        }
    }
    float inv = 1.0f / ls[rl];
    float* ob = out + ((size_t)b * NT + (size_t)qt * 128 + grow) * NH + col0;
    #pragma unroll
    for (int j = 0; j < 4; j++)
        *(float4*)(ob + j*4) = make_float4(acc[j].x*inv, acc[j].y*inv,
                                           acc[j].z*inv, acc[j].w*inv);
}

// ---------------------------------------------------------------------------
extern "C" void kernel_launch(void* const* d_in, const int* in_sizes, int n_in,
                              void* d_out, int out_size) {
    const float* x  = (const float*)d_in[0];
    const float* Wq = (const float*)d_in[1];
    const float* Wk = (const float*)d_in[2];
    const float* Wv = (const float*)d_in[3];
    float* out = (float*)d_out;

    wsplit<<<48, 256>>>(Wq, Wk, Wv);

    cudaFuncSetAttribute(qkv_tc, cudaFuncAttributeMaxDynamicSharedMemorySize, QK_SMEM);
    qkv_tc<<<128, 512, QK_SMEM>>>(x);

    cudaFuncSetAttribute(attn_tc, cudaFuncAttributeMaxDynamicSharedMemorySize, AT_SMEM);
    attn_tc<<<dim3(40, NB), 256, AT_SMEM>>>(out);

    combine<<<dim3(24, NB), 256>>>(out);
}